// round 7
// baseline (speedup 1.0000x reference)
#include <cuda_runtime.h>

// TransformDomainInterpolator, GB300 (sm_103a).
//
// Identity: fc = M/2 keeps ALL 2048 DFT bins, so the ortho FFT -> zero-pad ->
// sqrt(2)*ortho IFFT chain is exact 2x bandlimited interpolation:
//   out[2m]   = x[m]                                     (exact copy)
//   out[2m+1] = IDFT2048( DFT2048(x)[k] * w[k] ) / 2048,
//               w[k] = e^{+i*pi*k/2048} for k<1024, -e^{+i*pi*k/2048} for k>=1024
// Time axis: out[t] = lerp(H2, H11, a_t), a_t = clamp((t-2)/9, 0, 1).
//
// Output dtype handling: reference returns complex64 but the harness only has
// real dtypes. Dispatch on out_size:
//   out_size == B*14*4096   (f32)  -> real part only   (float2 pair stores)
//   out_size == B*14*4096*2 (f32)  -> interleaved re/im (float4 pair stores)
//
// One block per batch element; 40KB static smem; 4 blocks/SM.

#define THREADS 512
#define MM 2048          // pilots per pilot symbol
#define NSYM 14
#define RPT 4            // MM / THREADS

static __device__ __forceinline__ float2 cmul(float2 a, float2 b) {
    return make_float2(fmaf(a.x, b.x, -a.y * b.y), fmaf(a.x, b.y, a.y * b.x));
}
static __device__ __forceinline__ float2 cadd(float2 a, float2 b) {
    return make_float2(a.x + b.x, a.y + b.y);
}
static __device__ __forceinline__ float2 csub(float2 a, float2 b) {
    return make_float2(a.x - b.x, a.y - b.y);
}

// MODE 0: real-only f32 output. MODE 1: interleaved complex-as-f32 output.
template <int MODE>
__global__ void __launch_bounds__(THREADS) tdi_kernel(
    const float* __restrict__ re,
    const float* __restrict__ im,
    void* __restrict__ outv)
{
    __shared__ float2 tw[1024];     // e^{-2*pi*i*t/2048}
    __shared__ float2 y2[MM];       // workspace -> odd-sample values, symbol 2
    __shared__ float2 y11[MM];      // workspace -> odd-sample values, symbol 11

    const int b   = blockIdx.x;
    const int tid = threadIdx.x;

    // Twiddle table
    for (int t = tid; t < 1024; t += THREADS) {
        float s, c;
        sincospif(-(float)t * (1.0f / 1024.0f), &s, &c);
        tw[t] = make_float2(c, s);
    }

    // Load pilots: input layout [B, 4096] = [sym2 2048 | sym11 2048].
    // Keep the raw pilot values (even outputs) in registers.
    const float* rb = re + (size_t)b * 4096;
    const float* ib = im + (size_t)b * 4096;
    float2 rx2[RPT], rx11[RPT];
    #pragma unroll
    for (int r = 0; r < RPT; ++r) {
        int m = tid + r * THREADS;
        rx2[r]  = make_float2(rb[m],      ib[m]);
        rx11[r] = make_float2(rb[MM + m], ib[MM + m]);
        y2[m]  = rx2[r];
        y11[m] = rx11[r];
    }
    __syncthreads();

    // ---- Forward DIF FFT (natural -> bit-reversed), both rows per stage
    for (int s = 10; s >= 0; --s) {
        const int h = 1 << s;
        #pragma unroll
        for (int it = 0; it < 2; ++it) {
            int q  = tid + it * THREADS;          // butterfly 0..1023
            int j  = q & (h - 1);
            int i0 = ((q >> s) << (s + 1)) | j;
            int i1 = i0 + h;
            float2 w = tw[j << (10 - s)];
            float2 u = y2[i0], v = y2[i1];
            y2[i0] = cadd(u, v);
            y2[i1] = cmul(csub(u, v), w);
            u = y11[i0]; v = y11[i1];
            y11[i0] = cadd(u, v);
            y11[i1] = cmul(csub(u, v), w);
        }
        __syncthreads();
    }

    // ---- Pointwise twiddle in bit-reversed order (includes 1/2048 scale).
    // Position p holds X[bitrev11(p)]; k >= 1024 <=> (p & 1).
    for (int p = tid; p < MM; p += THREADS) {
        int k = (int)(__brev((unsigned)p) >> 21);
        float sv, cv;
        sincospif((float)k * (1.0f / 2048.0f), &sv, &cv);
        float sc = (p & 1) ? -(1.0f / 2048.0f) : (1.0f / 2048.0f);
        float2 w = make_float2(cv * sc, sv * sc);
        y2[p]  = cmul(y2[p],  w);
        y11[p] = cmul(y11[p], w);
    }
    __syncthreads();

    // ---- Inverse DIT FFT (bit-reversed -> natural), conjugate twiddles
    for (int s = 0; s <= 10; ++s) {
        const int h = 1 << s;
        #pragma unroll
        for (int it = 0; it < 2; ++it) {
            int q  = tid + it * THREADS;
            int j  = q & (h - 1);
            int i0 = ((q >> s) << (s + 1)) | j;
            int i1 = i0 + h;
            float2 w0 = tw[j << (10 - s)];
            float2 w  = make_float2(w0.x, -w0.y);
            float2 u = y2[i0], v = cmul(y2[i1], w);
            y2[i0] = cadd(u, v);
            y2[i1] = csub(u, v);
            u = y11[i0]; v = cmul(y11[i1], w);
            y11[i0] = cadd(u, v);
            y11[i1] = csub(u, v);
        }
        __syncthreads();
    }

    // ---- Write 14 OFDM symbols, (even, odd) pairs -> coalesced stores.
    #pragma unroll
    for (int t = 0; t < NSYM; ++t) {
        float a = (t <= 2) ? 0.0f : (t >= 11 ? 1.0f : (float)(t - 2) * (1.0f / 9.0f));
        size_t base = ((size_t)b * NSYM + t) * MM;
        #pragma unroll
        for (int r = 0; r < RPT; ++r) {
            int m = tid + r * THREADS;
            float2 e2 = rx2[r], e1 = rx11[r];
            float2 d2 = y2[m],  d1 = y11[m];
            if (MODE == 0) {
                // real part only
                float2 v;
                v.x = fmaf(a, e1.x - e2.x, e2.x);   // even subcarrier, Re
                v.y = fmaf(a, d1.x - d2.x, d2.x);   // odd subcarrier,  Re
                ((float2*)outv)[base + m] = v;
            } else {
                float4 v;
                v.x = fmaf(a, e1.x - e2.x, e2.x);   // even Re
                v.y = fmaf(a, e1.y - e2.y, e2.y);   // even Im
                v.z = fmaf(a, d1.x - d2.x, d2.x);   // odd Re
                v.w = fmaf(a, d1.y - d2.y, d2.y);   // odd Im
                ((float4*)outv)[base + m] = v;
            }
        }
    }
}

extern "C" void kernel_launch(void* const* d_in, const int* in_sizes, int n_in,
                              void* d_out, int out_size)
{
    const float* re = (const float*)d_in[0];
    const float* im = (const float*)d_in[1];
    const int B = in_sizes[0] / 4096;                      // 512
    const long long interleaved = (long long)B * NSYM * 4096 * 2;  // floats if complex kept

    if ((long long)out_size >= interleaved)
        tdi_kernel<1><<<B, THREADS>>>(re, im, d_out);
    else
        tdi_kernel<0><<<B, THREADS>>>(re, im, d_out);
}

// round 8
// speedup vs baseline: 1.5660x; 1.5660x over previous
#include <cuda_runtime.h>

// TransformDomainInterpolator, GB300 (sm_103a).
//
// Math: fc = M/2 keeps ALL 2048 DFT bins -> the ortho FFT -> zero-pad ->
// sqrt(2)*ortho IFFT chain is exact 2x bandlimited interpolation:
//   out[2m]   = x[m]                                  (exact copy)
//   out[2m+1] = IDFT2048( DFT2048(x)[k] * w[k] )/2048,
//     w[k] = e^{+i*pi*k/2048} (k<1024), -e^{+i*pi*k/2048} (k>=1024)
// Time: out[t] = lerp(H2, H11, clamp((t-2)/9, 0, 1)).
//
// R7 ncu: L1/shared-bound (65.9%), DRAM 13.5% (output lives in L2).
// This version: fused radix-2 pairs (radix-4 style) in registers -> only
// 5 fwd + 1 mid + 5 inv smem exchange phases (first/last phases live in
// registers), 11 barriers instead of 23, padded smem indexing for <=2-way
// bank conflicts. Epilogue is pure register math + coalesced stores.

#define THREADS 512
#define MM 2048
#define NSYM 14
#define PADN 2176                 // 2048 + 2048/16 padding
#define PIDX(i) ((i) + ((i) >> 4))

static __device__ __forceinline__ float2 cmul(float2 a, float2 b) {
    return make_float2(fmaf(a.x, b.x, -a.y * b.y), fmaf(a.x, b.y, a.y * b.x));
}
static __device__ __forceinline__ float2 cadd(float2 a, float2 b) {
    return make_float2(a.x + b.x, a.y + b.y);
}
static __device__ __forceinline__ float2 csub(float2 a, float2 b) {
    return make_float2(a.x - b.x, a.y - b.y);
}

// Fused forward DIF stages (S+1 then S) on elements {i0, i0+h, i0+2h, i0+3h}.
template <int S>
static __device__ __forceinline__ void fwd_phase(float2* __restrict__ y,
                                                 const float2* __restrict__ tw,
                                                 int q)
{
    const int h1 = 1 << S;
    const int j  = q & (h1 - 1);
    const int i0 = ((q >> S) << (S + 2)) | j;
    float2 w  = tw[j << (9 - S)];
    float2 wm = make_float2(w.y, -w.x);          // -i * w
    float2 v  = tw[j << (10 - S)];
    float2 a = y[PIDX(i0)];
    float2 bb = y[PIDX(i0 + h1)];
    float2 c = y[PIDX(i0 + 2 * h1)];
    float2 d = y[PIDX(i0 + 3 * h1)];
    float2 a1 = cadd(a, c),  c1 = cmul(csub(a, c), w);
    float2 b1 = cadd(bb, d), d1 = cmul(csub(bb, d), wm);
    y[PIDX(i0)]          = cadd(a1, b1);
    y[PIDX(i0 + h1)]     = cmul(csub(a1, b1), v);
    y[PIDX(i0 + 2 * h1)] = cadd(c1, d1);
    y[PIDX(i0 + 3 * h1)] = cmul(csub(c1, d1), v);
}

// Fused inverse DIT stages (S then S+1), conjugate twiddles.
template <int S>
static __device__ __forceinline__ void inv_phase(float2* __restrict__ y,
                                                 const float2* __restrict__ tw,
                                                 int q)
{
    const int h1 = 1 << S;
    const int j  = q & (h1 - 1);
    const int i0 = ((q >> S) << (S + 2)) | j;
    float2 w   = tw[j << (9 - S)];
    float2 cw  = make_float2(w.x, -w.y);         // conj(w)
    float2 cw2 = make_float2(w.y, w.x);          // i * conj(w)
    float2 v0  = tw[j << (10 - S)];
    float2 cv  = make_float2(v0.x, -v0.y);
    float2 a = y[PIDX(i0)];
    float2 bb = y[PIDX(i0 + h1)];
    float2 c = y[PIDX(i0 + 2 * h1)];
    float2 d = y[PIDX(i0 + 3 * h1)];
    float2 t  = cmul(bb, cv);
    float2 a1 = cadd(a, t), b1 = csub(a, t);
    t = cmul(d, cv);
    float2 c1 = cadd(c, t), d1 = csub(c, t);
    t = cmul(c1, cw);
    y[PIDX(i0)]          = cadd(a1, t);
    y[PIDX(i0 + 2 * h1)] = csub(a1, t);
    t = cmul(d1, cw2);
    y[PIDX(i0 + h1)]     = cadd(b1, t);
    y[PIDX(i0 + 3 * h1)] = csub(b1, t);
}

// MODE 0: real-only f32 output. MODE 1: interleaved complex-as-f32 output.
template <int MODE>
__global__ void __launch_bounds__(THREADS) tdi_kernel(
    const float* __restrict__ re,
    const float* __restrict__ im,
    void* __restrict__ outv)
{
    __shared__ float2 tw[1024];          // e^{-i*pi*t/1024}
    __shared__ float2 y2s[PADN];
    __shared__ float2 y11s[PADN];

    const int b = blockIdx.x;
    const int q = threadIdx.x;

    for (int t = q; t < 1024; t += THREADS) {
        float s, c;
        sincospif(-(float)t * (1.0f / 1024.0f), &s, &c);
        tw[t] = make_float2(c, s);
    }

    // Load pilots [B,4096] = [sym2 | sym11]; keep in regs (even outputs).
    const float* rb = re + (size_t)b * 4096;
    const float* ib = im + (size_t)b * 4096;
    float2 A2[4], A11[4];
    #pragma unroll
    for (int r = 0; r < 4; ++r) {
        int m = q + r * THREADS;
        A2[r]  = make_float2(rb[m],      ib[m]);
        A11[r] = make_float2(rb[MM + m], ib[MM + m]);
    }
    __syncthreads();   // tw ready

    // ---- FWD phase S=9 straight from registers (layout q + r*512)
    {
        float2 w  = tw[q];
        float2 wm = make_float2(w.y, -w.x);
        float2 v  = tw[2 * q];
        #pragma unroll
        for (int row = 0; row < 2; ++row) {
            float2* y = row ? y11s : y2s;
            const float2* A = row ? A11 : A2;
            float2 a1 = cadd(A[0], A[2]), c1 = cmul(csub(A[0], A[2]), w);
            float2 b1 = cadd(A[1], A[3]), d1 = cmul(csub(A[1], A[3]), wm);
            y[PIDX(q)]        = cadd(a1, b1);
            y[PIDX(q + 512)]  = cmul(csub(a1, b1), v);
            y[PIDX(q + 1024)] = cadd(c1, d1);
            y[PIDX(q + 1536)] = cmul(csub(c1, d1), v);
        }
    }
    __syncthreads();

    fwd_phase<7>(y2s, tw, q); fwd_phase<7>(y11s, tw, q); __syncthreads();
    fwd_phase<5>(y2s, tw, q); fwd_phase<5>(y11s, tw, q); __syncthreads();
    fwd_phase<3>(y2s, tw, q); fwd_phase<3>(y11s, tw, q); __syncthreads();
    fwd_phase<1>(y2s, tw, q); fwd_phase<1>(y11s, tw, q); __syncthreads();

    // ---- MID: fwd s=0 (w=1) + pointwise twiddle + inv s=0 (w=1), fused.
    // Position p holds X[bitrev11(p)]; p even -> k<1024 (+), p odd -> k+1024 (-).
    #pragma unroll
    for (int pr = 0; pr < 2; ++pr) {
        int p = 4 * q + 2 * pr;
        int k = (int)(__brev((unsigned)p) >> 21);
        float sv, cv;
        sincospif((float)k * (1.0f / 2048.0f), &sv, &cv);
        float2 base  = make_float2(cv * (1.0f / 2048.0f), sv * (1.0f / 2048.0f));
        float2 baseo = make_float2(base.y, -base.x);       // -i * base
        #pragma unroll
        for (int row = 0; row < 2; ++row) {
            float2* y = row ? y11s : y2s;
            float2 a = y[PIDX(p)], bb = y[PIDX(p + 1)];
            float2 A = cmul(cadd(a, bb), base);
            float2 Bv = cmul(csub(a, bb), baseo);
            y[PIDX(p)]     = cadd(A, Bv);
            y[PIDX(p + 1)] = csub(A, Bv);
        }
    }
    __syncthreads();

    inv_phase<1>(y2s, tw, q); inv_phase<1>(y11s, tw, q); __syncthreads();
    inv_phase<3>(y2s, tw, q); inv_phase<3>(y11s, tw, q); __syncthreads();
    inv_phase<5>(y2s, tw, q); inv_phase<5>(y11s, tw, q); __syncthreads();
    inv_phase<7>(y2s, tw, q); inv_phase<7>(y11s, tw, q); __syncthreads();

    // ---- INV phase S=9 into registers (natural order: index q + r*512).
    float2 D2[4], D11[4];
    {
        float2 w   = tw[q];
        float2 cw  = make_float2(w.x, -w.y);
        float2 cw2 = make_float2(w.y, w.x);
        float2 v0  = tw[2 * q];
        float2 cv  = make_float2(v0.x, -v0.y);
        #pragma unroll
        for (int row = 0; row < 2; ++row) {
            const float2* y = row ? y11s : y2s;
            float2* D = row ? D11 : D2;
            float2 a = y[PIDX(q)];
            float2 bb = y[PIDX(q + 512)];
            float2 c = y[PIDX(q + 1024)];
            float2 d = y[PIDX(q + 1536)];
            float2 t  = cmul(bb, cv);
            float2 a1 = cadd(a, t), b1 = csub(a, t);
            t = cmul(d, cv);
            float2 c1 = cadd(c, t), d1 = csub(c, t);
            t = cmul(c1, cw);
            D[0] = cadd(a1, t);
            D[2] = csub(a1, t);
            t = cmul(d1, cw2);
            D[1] = cadd(b1, t);
            D[3] = csub(b1, t);
        }
    }

    // ---- Epilogue: pure register math, coalesced (even,odd)-pair stores.
    #pragma unroll
    for (int t = 0; t < NSYM; ++t) {
        float a = (t <= 2) ? 0.0f : (t >= 11 ? 1.0f : (float)(t - 2) * (1.0f / 9.0f));
        size_t base = ((size_t)b * NSYM + t) * MM;
        #pragma unroll
        for (int r = 0; r < 4; ++r) {
            int m = q + r * THREADS;
            float2 e2 = A2[r], e1 = A11[r];
            float2 d2 = D2[r], d1 = D11[r];
            if (MODE == 0) {
                float2 v;
                v.x = fmaf(a, e1.x - e2.x, e2.x);   // even Re
                v.y = fmaf(a, d1.x - d2.x, d2.x);   // odd Re
                ((float2*)outv)[base + m] = v;
            } else {
                float4 v;
                v.x = fmaf(a, e1.x - e2.x, e2.x);
                v.y = fmaf(a, e1.y - e2.y, e2.y);
                v.z = fmaf(a, d1.x - d2.x, d2.x);
                v.w = fmaf(a, d1.y - d2.y, d2.y);
                ((float4*)outv)[base + m] = v;
            }
        }
    }
}

extern "C" void kernel_launch(void* const* d_in, const int* in_sizes, int n_in,
                              void* d_out, int out_size)
{
    const float* re = (const float*)d_in[0];
    const float* im = (const float*)d_in[1];
    const int B = in_sizes[0] / 4096;
    const long long interleaved = (long long)B * NSYM * 4096 * 2;

    if ((long long)out_size >= interleaved)
        tdi_kernel<1><<<B, THREADS>>>(re, im, d_out);
    else
        tdi_kernel<0><<<B, THREADS>>>(re, im, d_out);
}